// round 3
// baseline (speedup 1.0000x reference)
#include <cuda_runtime.h>
#include <cstdint>

// Problem shape: x [8,4096,512] f32, codebook [4096,512] f32
//   N = 32768 tokens, M = 4096 codes, D = 512
// Outputs concatenated in d_out (f32): q_st [N*D], commitment_loss [N], cb_n [M*D]

#define D_DIM 512
#define EPSN 1e-12f

// ---------------- device scratch (no allocations allowed) ----------------
__device__ float              g_cbn[4096 * 512];     // normalized codebook
__device__ float              g_invnx[32768];        // 1/max(||x_n||, eps)
__device__ unsigned long long g_best[32768];         // packed (flipped sim || ~idx)

// monotone float->uint mapping (order-preserving)
__device__ __forceinline__ unsigned flip_f(unsigned fb) {
    return (fb & 0x80000000u) ? ~fb : (fb | 0x80000000u);
}
__device__ __forceinline__ unsigned unflip_f(unsigned u) {
    return (u & 0x80000000u) ? (u & 0x7FFFFFFFu) : ~u;
}
__device__ __forceinline__ unsigned long long make_key(unsigned fbits, int idx) {
    return (((unsigned long long)flip_f(fbits)) << 32) |
           (unsigned long long)(0xFFFFFFFFu - (unsigned)idx);
}

// ---------------- kernel 1: normalize codebook rows ----------------
__global__ void norm_cb_kernel(const float* __restrict__ cb,
                               float* __restrict__ out_cb, int M) {
    int row = blockIdx.x;
    int tid = threadIdx.x;   // 128 threads, 4 floats each
    const float4 v = *(const float4*)(cb + (size_t)row * D_DIM + tid * 4);
    float s = v.x * v.x + v.y * v.y + v.z * v.z + v.w * v.w;
    #pragma unroll
    for (int off = 16; off > 0; off >>= 1)
        s += __shfl_down_sync(0xffffffffu, s, off);
    __shared__ float ws[4];
    __shared__ float sinv;
    if ((tid & 31) == 0) ws[tid >> 5] = s;
    __syncthreads();
    if (tid == 0) {
        float tot = ws[0] + ws[1] + ws[2] + ws[3];
        sinv = 1.0f / fmaxf(sqrtf(tot), EPSN);
    }
    __syncthreads();
    float inv = sinv;
    float4 o;
    o.x = v.x * inv; o.y = v.y * inv; o.z = v.z * inv; o.w = v.w * inv;
    *(float4*)(g_cbn + (size_t)row * D_DIM + tid * 4) = o;
    if (out_cb)
        *(float4*)(out_cb + (size_t)row * D_DIM + tid * 4) = o;
}

// ---------------- kernel 2: x row inverse norms (+ init best) ----------------
__global__ void norm_x_kernel(const float* __restrict__ x, int N) {
    int row = blockIdx.x;
    int tid = threadIdx.x;
    const float4 v = *(const float4*)(x + (size_t)row * D_DIM + tid * 4);
    float s = v.x * v.x + v.y * v.y + v.z * v.z + v.w * v.w;
    #pragma unroll
    for (int off = 16; off > 0; off >>= 1)
        s += __shfl_down_sync(0xffffffffu, s, off);
    __shared__ float ws[4];
    if ((tid & 31) == 0) ws[tid >> 5] = s;
    __syncthreads();
    if (tid == 0) {
        float tot = ws[0] + ws[1] + ws[2] + ws[3];
        g_invnx[row] = 1.0f / fmaxf(sqrtf(tot), EPSN);
        g_best[row] = 0ull;
    }
}

// ---------------- kernel 3: fp32 GEMM (x . cb_n^T) + fused argmax ----------------
// 128x128 tile, TK=16, 256 threads, 8x8 microtile, packed f32x2 FMA,
// single-stage register prefetch of the next global tile.
#define TM 128
#define TN 128
#define TK 16

__global__ __launch_bounds__(256, 2)
void gemm_argmax_kernel(const float* __restrict__ A,   // [N, 512] raw x
                        const float* __restrict__ B,   // [M, 512] normalized cb
                        unsigned long long* __restrict__ best,
                        int K) {
    __shared__ float As[TK][TM + 4];   // stride 132 floats = 528B (16B-mult)
    __shared__ float Bs[TK][TN + 4];   // stride 132: LDS.128-friendly

    const int tid = threadIdx.x;
    const int tx = tid & 15;          // code-dim thread coord
    const int ty = tid >> 4;          // token-dim thread coord
    const int nBase = blockIdx.y * TM;
    const int mBase = blockIdx.x * TN;
    const int rowBase = ty * 8;
    const int colBase = tx * 8;

    // per-thread gmem load coords (2 float4 per operand per tile)
    const int ldn0 = tid >> 2,        ldk0 = (tid & 3) * 4;
    const int ldn1 = (tid + 256) >> 2, ldk1 = ((tid + 256) & 3) * 4;

    const float* Arow0 = A + (size_t)(nBase + ldn0) * K + ldk0;
    const float* Arow1 = A + (size_t)(nBase + ldn1) * K + ldk1;
    const float* Brow0 = B + (size_t)(mBase + ldn0) * K + ldk0;
    const float* Brow1 = B + (size_t)(mBase + ldn1) * K + ldk1;

    unsigned long long acc[8][4];
    #pragma unroll
    for (int i = 0; i < 8; i++)
        #pragma unroll
        for (int p = 0; p < 4; p++) acc[i][p] = 0ull;   // (0.0f, 0.0f)

    // preload tile 0
    float4 rA0 = *(const float4*)(Arow0);
    float4 rA1 = *(const float4*)(Arow1);
    float4 rB0 = *(const float4*)(Brow0);
    float4 rB1 = *(const float4*)(Brow1);

    for (int k0 = 0; k0 < K; k0 += TK) {
        // ---- store prefetched regs into SMEM (transposed) ----
        {
            int n = ldn0, kq = ldk0 >> 2;
            As[kq * 4 + 0][n] = rA0.x; As[kq * 4 + 1][n] = rA0.y;
            As[kq * 4 + 2][n] = rA0.z; As[kq * 4 + 3][n] = rA0.w;
            Bs[kq * 4 + 0][n] = rB0.x; Bs[kq * 4 + 1][n] = rB0.y;
            Bs[kq * 4 + 2][n] = rB0.z; Bs[kq * 4 + 3][n] = rB0.w;
            n = ldn1; kq = ldk1 >> 2;
            As[kq * 4 + 0][n] = rA1.x; As[kq * 4 + 1][n] = rA1.y;
            As[kq * 4 + 2][n] = rA1.z; As[kq * 4 + 3][n] = rA1.w;
            Bs[kq * 4 + 0][n] = rB1.x; Bs[kq * 4 + 1][n] = rB1.y;
            Bs[kq * 4 + 2][n] = rB1.z; Bs[kq * 4 + 3][n] = rB1.w;
        }
        __syncthreads();

        // ---- issue next tile's global loads (overlap with compute) ----
        if (k0 + TK < K) {
            rA0 = *(const float4*)(Arow0 + k0 + TK);
            rA1 = *(const float4*)(Arow1 + k0 + TK);
            rB0 = *(const float4*)(Brow0 + k0 + TK);
            rB1 = *(const float4*)(Brow1 + k0 + TK);
        }

        #pragma unroll
        for (int k = 0; k < TK; k++) {
            float a[8];
            *(float4*)(a)     = *(const float4*)(&As[k][rowBase]);
            *(float4*)(a + 4) = *(const float4*)(&As[k][rowBase + 4]);
            unsigned long long b[4];
            {
                ulonglong2 b01 = *(const ulonglong2*)(&Bs[k][colBase]);
                ulonglong2 b23 = *(const ulonglong2*)(&Bs[k][colBase + 4]);
                b[0] = b01.x; b[1] = b01.y; b[2] = b23.x; b[3] = b23.y;
            }
            #pragma unroll
            for (int i = 0; i < 8; i++) {
                unsigned long long pa;
                asm("mov.b64 %0, {%1, %1};" : "=l"(pa) : "r"(__float_as_uint(a[i])));
                #pragma unroll
                for (int p = 0; p < 4; p++) {
                    asm("fma.rn.f32x2 %0, %1, %2, %3;"
                        : "=l"(acc[i][p])
                        : "l"(pa), "l"(b[p]), "l"(acc[i][p]));
                }
            }
        }
        __syncthreads();
    }

    // ---- fused argmax epilogue ----
    #pragma unroll
    for (int i = 0; i < 8; i++) {
        unsigned long long bk = 0ull;
        #pragma unroll
        for (int p = 0; p < 4; p++) {
            unsigned lo = (unsigned)(acc[i][p] & 0xFFFFFFFFull);
            unsigned hi = (unsigned)(acc[i][p] >> 32);
            int c0 = mBase + colBase + 2 * p;
            unsigned long long k0p = make_key(lo, c0);
            unsigned long long k1p = make_key(hi, c0 + 1);
            if (k0p > bk) bk = k0p;
            if (k1p > bk) bk = k1p;
        }
        // reduce across the 16 code-dim lanes (half-warp segment = one ty)
        #pragma unroll
        for (int off = 8; off > 0; off >>= 1) {
            unsigned long long o = __shfl_down_sync(0xffffffffu, bk, off, 16);
            if (o > bk) bk = o;
        }
        if (tx == 0)
            atomicMax(&best[nBase + rowBase + i], bk);
    }
}

// ---------------- kernel 4: finalize (gather q_st + loss) ----------------
__global__ void finalize_kernel(float* __restrict__ q_out,
                                float* __restrict__ loss_out, int N) {
    int n = blockIdx.x;
    int tid = threadIdx.x;   // 128 threads, one float4 each
    unsigned long long pk = g_best[n];
    unsigned idx = 0xFFFFFFFFu - (unsigned)(pk & 0xFFFFFFFFull);
    float dot = __uint_as_float(unflip_f((unsigned)(pk >> 32)));
    float4 v = *(const float4*)(g_cbn + (size_t)idx * D_DIM + tid * 4);
    *(float4*)(q_out + (size_t)n * D_DIM + tid * 4) = v;
    if (tid == 0 && loss_out)
        loss_out[n] = 1.0f - dot * g_invnx[n];
}

// ---------------- host launch ----------------
extern "C" void kernel_launch(void* const* d_in, const int* in_sizes, int n_in,
                              void* d_out, int out_size) {
    const float* x  = (const float*)d_in[0];
    const float* cb = (const float*)d_in[1];
    const int N = in_sizes[0] / D_DIM;   // 32768
    const int M = in_sizes[1] / D_DIM;   // 4096

    float* out = (float*)d_out;
    float* q_out = out;
    float* loss_out = nullptr;
    float* cb_out = nullptr;
    long long need_full = (long long)N * D_DIM + N + (long long)M * D_DIM;
    if ((long long)out_size >= need_full) {
        loss_out = out + (size_t)N * D_DIM;
        cb_out = loss_out + N;
    } else if ((long long)out_size >= (long long)N * D_DIM + N) {
        loss_out = out + (size_t)N * D_DIM;
    }

    // CRITICAL: device-symbol addresses must come from cudaGetSymbolAddress;
    // naming a __device__ symbol in host code passes the host shadow (and on
    // GB300 ATS that READS HOST MEMORY silently instead of faulting).
    float* cbn_p = nullptr;
    cudaGetSymbolAddress((void**)&cbn_p, g_cbn);
    unsigned long long* bestp = nullptr;
    cudaGetSymbolAddress((void**)&bestp, g_best);

    norm_cb_kernel<<<M, 128>>>(cb, cb_out, M);
    norm_x_kernel<<<N, 128>>>(x, N);

    dim3 grid(M / TN, N / TM);
    gemm_argmax_kernel<<<grid, 256>>>(x, cbn_p, bestp, D_DIM);

    finalize_kernel<<<N, 128>>>(q_out, loss_out, N);
}

// round 6
// speedup vs baseline: 2.0143x; 2.0143x over previous
#include <cuda_runtime.h>
#include <cuda_fp16.h>
#include <cstdint>

// Problem: x [8,4096,512] f32, codebook [4096,512] f32
//   N = 32768 tokens, M = 4096 codes, K = 512
// Out (f32, concatenated): q_st [N*512], commitment_loss [N], cb_n [M*512]
//
// argmax_m cos(x, cb_m) via fp16 3-block limb GEMM on mma.sync (HMMA):
//   A' = [Hx | Mx*32 | Hx/32]  (K'=1536)     (H,M = RN fp16 hi/mid limbs)
//   B' = [Hc | Hc/32 | Mc*32]  (raw codebook)
//   A'.B' = Hx.Hc + Mx.Hc + Hx.Mc = (x - rx).(c - rc) + tiny
// Epilogue rescales column m by 1/||cb_m|| (cosine), then fused argmax.

#define NTOK   32768
#define MCODE  4096
#define KDIM   512
#define KSPLIT 1536
#define EPSN   1e-12f

#define TILE        128
#define KC          64                      // fp16 per k-chunk (128 B rows)
#define NSTAGE      3
#define ATILE_BYTES (TILE * 128)            // 16384
#define STAGE_BYTES (2 * ATILE_BYTES)       // A + B
#define DYN_SMEM    (NSTAGE * STAGE_BYTES)  // 98304
#define NITER       (KSPLIT / KC)           // 24

// ---------------- device scratch (no allocs allowed) ----------------
__device__ __half             g_xs[(size_t)NTOK * KSPLIT];
__device__ __half             g_bs[(size_t)MCODE * KSPLIT];
__device__ float              g_cbn[(size_t)MCODE * KDIM];   // normalized cb
__device__ float              g_invnb[MCODE];                // 1/max(||cb||,eps)
__device__ float              g_invnx[NTOK];
__device__ unsigned long long g_best[NTOK];

// ---------------- helpers ----------------
__device__ __forceinline__ uint32_t smem_u32(const void* p) {
    uint32_t a;
    asm("{ .reg .u64 t; cvta.to.shared.u64 t, %1; cvt.u32.u64 %0, t; }"
        : "=r"(a) : "l"(p));
    return a;
}
__device__ __forceinline__ void cp_async16(uint32_t s, const void* g) {
    asm volatile("cp.async.cg.shared.global [%0], [%1], 16;" :: "r"(s), "l"(g));
}
__device__ __forceinline__ void ldsm_x4(uint32_t* r, uint32_t addr) {
    asm volatile("ldmatrix.sync.aligned.m8n8.x4.shared.b16 {%0,%1,%2,%3}, [%4];"
                 : "=r"(r[0]), "=r"(r[1]), "=r"(r[2]), "=r"(r[3]) : "r"(addr));
}
__device__ __forceinline__ void mma16816(float* c, const uint32_t* a,
                                         const uint32_t* b) {
    asm volatile(
        "mma.sync.aligned.m16n8k16.row.col.f32.f16.f16.f32 "
        "{%0,%1,%2,%3}, {%4,%5,%6,%7}, {%8,%9}, {%0,%1,%2,%3};"
        : "+f"(c[0]), "+f"(c[1]), "+f"(c[2]), "+f"(c[3])
        : "r"(a[0]), "r"(a[1]), "r"(a[2]), "r"(a[3]), "r"(b[0]), "r"(b[1]));
}

// monotone float<->uint (order-preserving); key = (flipped dot || ~idx)
__device__ __forceinline__ unsigned flip_f(unsigned fb) {
    return (fb & 0x80000000u) ? ~fb : (fb | 0x80000000u);
}
__device__ __forceinline__ unsigned unflip_f(unsigned u) {
    return (u & 0x80000000u) ? (u & 0x7FFFFFFFu) : ~u;
}
__device__ __forceinline__ unsigned long long make_key(unsigned fbits, int idx) {
    return (((unsigned long long)flip_f(fbits)) << 32) |
           (unsigned long long)(0xFFFFFFFFu - (unsigned)idx);
}

// 3-limb store: dst[0]=H, dst[off1]=RN16(32(f-H)), dst[off2]=H/32 (exact-ish)
__device__ __forceinline__ void split_store(float f, __half* d0, __half* d1,
                                            __half* d2) {
    __half h = __float2half_rn(f);
    float hf = __half2float(h);
    *d0 = h;
    *d1 = __float2half_rn((f - hf) * 32.0f);   // Mx*32 (finer grid: exact pairing)
    *d2 = __float2half_rn(hf * 0.03125f);      // Hx/32 (exact shift in range)
}

// ---------------- kernel 1: codebook norms + normalized copy + limbs ----------------
__global__ void norm_cb_kernel(const float* __restrict__ cb,
                               float* __restrict__ out_cb) {
    int row = blockIdx.x;
    int tid = threadIdx.x;   // 128 threads x 4 floats
    const float4 v = *(const float4*)(cb + (size_t)row * KDIM + tid * 4);
    float s = v.x * v.x + v.y * v.y + v.z * v.z + v.w * v.w;
    #pragma unroll
    for (int off = 16; off > 0; off >>= 1) s += __shfl_down_sync(~0u, s, off);
    __shared__ float ws[4]; __shared__ float sinv;
    if ((tid & 31) == 0) ws[tid >> 5] = s;
    __syncthreads();
    if (tid == 0) {
        float inv = 1.0f / fmaxf(sqrtf(ws[0] + ws[1] + ws[2] + ws[3]), EPSN);
        sinv = inv;
        g_invnb[row] = inv;
    }
    __syncthreads();
    float inv = sinv;
    float o[4] = {v.x * inv, v.y * inv, v.z * inv, v.w * inv};
    size_t fb = (size_t)row * KDIM + tid * 4;
    *(float4*)(g_cbn + fb) = *(float4*)o;
    if (out_cb) *(float4*)(out_cb + fb) = *(float4*)o;
    // raw-cb limbs: [Hc | Hc/32 | Mc*32]
    float f[4] = {v.x, v.y, v.z, v.w};
    __half* base = g_bs + (size_t)row * KSPLIT + tid * 4;
    #pragma unroll
    for (int j = 0; j < 4; j++) {
        __half h = __float2half_rn(f[j]);
        float hf = __half2float(h);
        base[j]        = h;
        base[512 + j]  = __float2half_rn(hf * 0.03125f);
        base[1024 + j] = __float2half_rn((f[j] - hf) * 32.0f);
    }
}

// ---------------- kernel 2: x inv-norms + limbs + init best ----------------
__global__ void norm_x_kernel(const float* __restrict__ x) {
    int row = blockIdx.x;
    int tid = threadIdx.x;
    const float4 v = *(const float4*)(x + (size_t)row * KDIM + tid * 4);
    float s = v.x * v.x + v.y * v.y + v.z * v.z + v.w * v.w;
    #pragma unroll
    for (int off = 16; off > 0; off >>= 1) s += __shfl_down_sync(~0u, s, off);
    __shared__ float ws[4];
    if ((tid & 31) == 0) ws[tid >> 5] = s;
    __syncthreads();
    if (tid == 0) {
        g_invnx[row] = 1.0f / fmaxf(sqrtf(ws[0] + ws[1] + ws[2] + ws[3]), EPSN);
        g_best[row] = 0ull;
    }
    // x limbs: [Hx | Mx*32 | Hx/32]
    float f[4] = {v.x, v.y, v.z, v.w};
    __half* base = g_xs + (size_t)row * KSPLIT + tid * 4;
    #pragma unroll
    for (int j = 0; j < 4; j++) {
        __half h = __float2half_rn(f[j]);
        float hf = __half2float(h);
        base[j]        = h;
        base[512 + j]  = __float2half_rn((f[j] - hf) * 32.0f);
        base[1024 + j] = __float2half_rn(hf * 0.03125f);
    }
}

// ---------------- kernel 3: HMMA GEMM (K'=1536) + cosine rescale + argmax ----------------
// grid (MCODE/TILE=32 inner, NTOK/TILE=256); 256 threads; warp tile 32x64.
extern "C" __global__ void __launch_bounds__(256, 2)
vq_hmma_kernel(unsigned long long* __restrict__ best) {
    extern __shared__ char smem[];
    __shared__ unsigned long long s_best[TILE];
    __shared__ float s_invb[TILE];

    const int tid = threadIdx.x;
    const int wid = tid >> 5;
    const int lid = tid & 31;
    const int mBase = blockIdx.x * TILE;   // codes
    const int nBase = blockIdx.y * TILE;   // tokens

    if (tid < TILE) {
        s_best[tid] = 0ull;
        s_invb[tid] = g_invnb[mBase + tid];
    }

    const uint32_t sbase = smem_u32(smem);

    // ---- cp.async coordinates: thread -> (row, 64B-half), 4x16B each op ----
    const int ldrow = tid >> 1;
    const int ldhalf = tid & 1;
    const __half* aSrc = g_xs + (size_t)(nBase + ldrow) * KSPLIT + ldhalf * 32;
    const __half* bSrc = g_bs + (size_t)(mBase + ldrow) * KSPLIT + ldhalf * 32;
    uint32_t aDst[4], bDst[4];
    {
        const uint32_t xr = (ldrow & 7) << 4;   // SW128 xor
        #pragma unroll
        for (int q = 0; q < 4; q++) {
            uint32_t cbyte = ldhalf * 64 + q * 16;
            uint32_t off = ldrow * 128 + (cbyte ^ xr);
            aDst[q] = off;
            bDst[q] = ATILE_BYTES + off;
        }
    }

    // ---- ldmatrix lane addressing ----
    const int wRow = (wid & 3) * 32;   // token rows of this warp
    const int wCol = (wid >> 2) * 64;  // code cols of this warp
    uint32_t aRowOff[2], aXor[2];
    #pragma unroll
    for (int mt = 0; mt < 2; mt++) {
        int r = wRow + mt * 16 + (lid & 7) + ((lid >> 3) & 1) * 8;
        aRowOff[mt] = r * 128;
        aXor[mt] = (r & 7) << 4;
    }
    const uint32_t aCb = ((lid >> 4) & 1) * 16;
    uint32_t bRowOff[4], bXor[4];
    #pragma unroll
    for (int np = 0; np < 4; np++) {
        int r = wCol + np * 16 + (lid & 7) + ((lid >> 4) & 1) * 8;
        bRowOff[np] = ATILE_BYTES + r * 128;
        bXor[np] = (r & 7) << 4;
    }
    const uint32_t bCb = ((lid >> 3) & 1) * 16;

    float acc[2][8][4];
    #pragma unroll
    for (int mt = 0; mt < 2; mt++)
        #pragma unroll
        for (int nt = 0; nt < 8; nt++)
            #pragma unroll
            for (int j = 0; j < 4; j++) acc[mt][nt][j] = 0.0f;

#define ISSUE(stage, bufi) do {                                           \
        uint32_t sb_ = sbase + (bufi) * STAGE_BYTES;                      \
        const __half* a_ = aSrc + (stage) * KC;                           \
        const __half* b_ = bSrc + (stage) * KC;                           \
        _Pragma("unroll")                                                 \
        for (int q = 0; q < 4; q++) cp_async16(sb_ + aDst[q], a_ + q * 8);\
        _Pragma("unroll")                                                 \
        for (int q = 0; q < 4; q++) cp_async16(sb_ + bDst[q], b_ + q * 8);\
    } while (0)

    // prologue: stages 0..2
    #pragma unroll
    for (int s = 0; s < NSTAGE; s++) {
        ISSUE(s, s);
        asm volatile("cp.async.commit_group;" ::: "memory");
    }

    int buf = 0;
    for (int i = 0; i < NITER; i++) {
        asm volatile("cp.async.wait_group 2;" ::: "memory");
        __syncthreads();

        const uint32_t sb = sbase + buf * STAGE_BYTES;
        #pragma unroll
        for (int ks = 0; ks < 4; ks++) {
            uint32_t a[2][4];
            #pragma unroll
            for (int mt = 0; mt < 2; mt++)
                ldsm_x4(a[mt], sb + aRowOff[mt] + (((uint32_t)ks * 32 + aCb) ^ aXor[mt]));
            uint32_t b[4][4];
            #pragma unroll
            for (int np = 0; np < 4; np++)
                ldsm_x4(b[np], sb + bRowOff[np] + (((uint32_t)ks * 32 + bCb) ^ bXor[np]));
            #pragma unroll
            for (int mt = 0; mt < 2; mt++)
                #pragma unroll
                for (int nt = 0; nt < 8; nt++)
                    mma16816(acc[mt][nt], a[mt], &b[nt >> 1][(nt & 1) * 2]);
        }
        __syncthreads();

        if (i + NSTAGE < NITER) ISSUE(i + NSTAGE, buf);
        asm volatile("cp.async.commit_group;" ::: "memory");
        buf = (buf == NSTAGE - 1) ? 0 : buf + 1;
    }

    // ---- cosine rescale + fused argmax ----
    #pragma unroll
    for (int mt = 0; mt < 2; mt++) {
        #pragma unroll
        for (int sub = 0; sub < 2; sub++) {
            unsigned long long bk = 0ull;
            #pragma unroll
            for (int nt = 0; nt < 8; nt++) {
                #pragma unroll
                for (int j = 0; j < 2; j++) {
                    int cl = wCol + nt * 8 + 2 * (lid & 3) + j;
                    float f = acc[mt][nt][sub * 2 + j] * s_invb[cl];
                    unsigned long long k = make_key(__float_as_uint(f), mBase + cl);
                    if (k > bk) bk = k;
                }
            }
            unsigned long long o;
            o = __shfl_xor_sync(~0u, bk, 1); if (o > bk) bk = o;
            o = __shfl_xor_sync(~0u, bk, 2); if (o > bk) bk = o;
            if ((lid & 3) == 0) {
                int rowLocal = wRow + mt * 16 + sub * 8 + (lid >> 2);
                atomicMax(&s_best[rowLocal], bk);
            }
        }
    }
    __syncthreads();
    if (tid < TILE)
        atomicMax(&best[nBase + tid], s_best[tid]);
}

// ---------------- kernel 4: finalize (gather q_st + loss) ----------------
__global__ void finalize_kernel(float* __restrict__ q_out,
                                float* __restrict__ loss_out) {
    int n = blockIdx.x;
    int tid = threadIdx.x;   // 128 threads, one float4 each
    unsigned long long pk = g_best[n];
    unsigned idx = 0xFFFFFFFFu - (unsigned)(pk & 0xFFFFFFFFull);
    float dot = __uint_as_float(unflip_f((unsigned)(pk >> 32)));  // = x.cb_norm
    float4 v = *(const float4*)(g_cbn + (size_t)idx * KDIM + tid * 4);
    *(float4*)(q_out + (size_t)n * KDIM + tid * 4) = v;
    if (tid == 0 && loss_out)
        loss_out[n] = 1.0f - dot * g_invnx[n];
}

// ---------------- host launch ----------------
extern "C" void kernel_launch(void* const* d_in, const int* in_sizes, int n_in,
                              void* d_out, int out_size) {
    const float* x  = (const float*)d_in[0];
    const float* cb = (const float*)d_in[1];
    const int N = in_sizes[0] / KDIM;   // 32768
    const int M = in_sizes[1] / KDIM;   // 4096

    float* out = (float*)d_out;
    float* q_out = out;
    float* loss_out = nullptr;
    float* cb_out = nullptr;
    long long need_full = (long long)N * KDIM + N + (long long)M * KDIM;
    if ((long long)out_size >= need_full) {
        loss_out = out + (size_t)N * KDIM;
        cb_out = loss_out + N;
    } else if ((long long)out_size >= (long long)N * KDIM + N) {
        loss_out = out + (size_t)N * KDIM;
    }

    cudaFuncSetAttribute(vq_hmma_kernel,
                         cudaFuncAttributeMaxDynamicSharedMemorySize, DYN_SMEM);

    // device-symbol addresses MUST come from cudaGetSymbolAddress (R1 lesson)
    unsigned long long* bestp = nullptr;
    cudaGetSymbolAddress((void**)&bestp, g_best);

    norm_cb_kernel<<<M, 128>>>(cb, cb_out);
    norm_x_kernel<<<N, 128>>>(x);

    dim3 grid(M / TILE, N / TILE);   // codes inner -> B' (12 MB) stays hot in L2
    vq_hmma_kernel<<<grid, 256, DYN_SMEM>>>(bestp);

    finalize_kernel<<<N, 128>>>(q_out, loss_out);
}